// round 10
// baseline (speedup 1.0000x reference)
#include <cuda_runtime.h>
#include <cuda_bf16.h>
#include <stdint.h>

typedef unsigned long long u64;

#define BB   2
#define SS   2048
#define MM   (BB * SS)
#define HH   512
#define VV   32000
#define KK   300
#define CAP  1024
#define T_CAND 2.20f
#define T_SAFE 2.26f

// ---------------- scratch (device globals) --------------------------------
__device__ unsigned g_keys[(size_t)MM * VV];
__device__ float    g_wt[(size_t)VV * HH];
__device__ float    g_wtb[(size_t)VV * HH];
__device__ __nv_bfloat16 a_bf[(size_t)MM * HH];
__device__ __nv_bfloat16 b_bf[(size_t)VV * HH];
__device__ int      g_topk[(size_t)MM * KK];
__device__ int      g_cidx[(size_t)MM * CAP];
__device__ u64      g_cand[(size_t)MM * CAP];
__device__ int      g_cnt[MM];
__device__ int      g_flag[MM];
__device__ float    g_thr[MM];
__device__ unsigned g_keysafe[MM];

// ---------------- XLA fast-tanh (BIT-EXACT — FROZEN) ----------------------
__device__ __forceinline__ float xla_tanh(float v) {
    float ax = fabsf(v);
    float x  = fminf(fmaxf(v, -7.99881172180175781f), 7.99881172180175781f);
    float x2 = __fmul_rn(x, x);
    float p = __fmaf_rn(x2, -2.76076847742355e-16f, 2.00018790482477e-13f);
    p = __fmaf_rn(x2, p, -8.60467152213735e-11f);
    p = __fmaf_rn(x2, p,  5.12229709037114e-08f);
    p = __fmaf_rn(x2, p,  1.48572235717979e-05f);
    p = __fmaf_rn(x2, p,  6.37261928875436e-04f);
    p = __fmaf_rn(x2, p,  4.89352455891786e-03f);
    p = __fmul_rn(x, p);
    float q = __fmaf_rn(x2, 1.19825839466702e-06f, 1.18534705686654e-04f);
    q = __fmaf_rn(x2, q, 2.26843463243900e-03f);
    q = __fmaf_rn(x2, q, 4.89352518554385e-03f);
    float r = __fdiv_rn(p, q);
    return (ax < 0.0004f) ? v : r;
}

__device__ __forceinline__ unsigned fkey(float f) {
    unsigned u = __float_as_uint(f);
    return (u & 0x80000000u) ? ~u : (u | 0x80000000u);
}

// ---------------- async copy / ldmatrix helpers ----------------------------
__device__ __forceinline__ void cp_async16(void* smem, const void* gmem) {
    unsigned s = (unsigned)__cvta_generic_to_shared(smem);
    asm volatile("cp.async.cg.shared.global [%0], [%1], 16;" :: "r"(s), "l"(gmem));
}
__device__ __forceinline__ void ldsm_x4(unsigned& r0, unsigned& r1,
                                        unsigned& r2, unsigned& r3, unsigned saddr) {
    asm volatile("ldmatrix.sync.aligned.m8n8.x4.shared.b16 {%0,%1,%2,%3}, [%4];"
        : "=r"(r0), "=r"(r1), "=r"(r2), "=r"(r3) : "r"(saddr));
}

// ---------------- row norms + bf16 convert of hs --------------------------
__global__ __launch_bounds__(256) void prep_kernel(const float* __restrict__ hs) {
    const int row = blockIdx.x, tid = threadIdx.x;
    const float* h = hs + (size_t)row * HH;
    float v0 = h[tid], v1 = h[tid + 256];
    a_bf[(size_t)row * HH + tid]       = __float2bfloat16(v0);
    a_bf[(size_t)row * HH + tid + 256] = __float2bfloat16(v1);
    __shared__ float red[256];
    red[tid] = v0 * v0 + v1 * v1;
    __syncthreads();
    for (int o = 128; o > 0; o >>= 1) {
        if (tid < o) red[tid] += red[tid + o];
        __syncthreads();
    }
    if (tid == 0) {
        float s = sqrtf(red[0] / (float)HH);
        g_thr[row] = T_CAND * s;
        g_keysafe[row] = fkey(xla_tanh(xla_tanh(T_SAFE * s)));
    }
}

// ---------------- transposes ----------------------------------------------
__global__ void transpose_wout(const float* __restrict__ W) {
    __shared__ float tile[32][33];
    int x = blockIdx.x * 32 + threadIdx.x;
    int y = blockIdx.y * 32 + threadIdx.y;
#pragma unroll
    for (int i = 0; i < 32; i += 8)
        tile[threadIdx.y + i][threadIdx.x] = W[(size_t)(y + i) * VV + x];
    __syncthreads();
    int xo = blockIdx.y * 32 + threadIdx.x;
    int yo = blockIdx.x * 32 + threadIdx.y;
#pragma unroll
    for (int i = 0; i < 32; i += 8)
        g_wt[(size_t)(yo + i) * HH + xo] = tile[threadIdx.x][threadIdx.y + i];
}

__global__ void transpose_wbin(const float* __restrict__ W) {
    __shared__ float tile[32][33];
    int x = blockIdx.x * 32 + threadIdx.x;
    int y = blockIdx.y * 32 + threadIdx.y;
#pragma unroll
    for (int i = 0; i < 32; i += 8)
        tile[threadIdx.y + i][threadIdx.x] = W[(size_t)(y + i) * VV + x];
    __syncthreads();
    int xo = blockIdx.y * 32 + threadIdx.x;
    int yo = blockIdx.x * 32 + threadIdx.y;
#pragma unroll
    for (int i = 0; i < 32; i += 8) {
        float v = tile[threadIdx.x][threadIdx.y + i];
        g_wtb[(size_t)(yo + i) * HH + xo] = v;
        b_bf[(size_t)(yo + i) * HH + xo]  = __float2bfloat16(v);
    }
}

// ---------------- bf16 tensor-core GEMM (cp.async + ldmatrix, KSTEP=64) ---
#define KSTEP 64
#define SSTR  72
#define STAGE_ELEMS (128 * SSTR)
__global__ __launch_bounds__(256) void mma_kernel() {
    __shared__ __align__(16) unsigned short As[2][STAGE_ELEMS];
    __shared__ __align__(16) unsigned short Bs[2][STAGE_ELEMS];

    const int tid  = threadIdx.x;
    const int warp = tid >> 5, lane = tid & 31;
    const int wm = warp & 1, wn = warp >> 1;
    const int gid = lane >> 2, qid = lane & 3;
    const int m0 = blockIdx.y * 128, n0 = blockIdx.x * 128;

    float c[4][4][4];
#pragma unroll
    for (int mi = 0; mi < 4; mi++)
#pragma unroll
        for (int ni = 0; ni < 4; ni++)
#pragma unroll
            for (int v = 0; v < 4; v++) c[mi][ni][v] = 0.f;

    const unsigned short* Ag = (const unsigned short*)a_bf + (size_t)m0 * HH;
    const unsigned short* Bg = (const unsigned short*)b_bf + (size_t)n0 * HH;
    // tile 128 rows x 64 cols bf16: 2 threads per row, 4 uint4 each
    const int lr = tid >> 1, lc = (tid & 1) * 32;

    const int lrow8 = ((lane >> 3) & 1) * 8 + (lane & 7);
    const int lcol8 = (lane >> 4) * 8;
    const unsigned aSmem = (unsigned)__cvta_generic_to_shared(&As[0][0]);
    const unsigned bSmem = (unsigned)__cvta_generic_to_shared(&Bs[0][0]);
    const unsigned laneA = ((unsigned)((wm * 64 + lrow8) * SSTR + lcol8)) * 2u;
    const unsigned laneB = ((unsigned)((wn * 32 + lrow8) * SSTR + lcol8)) * 2u;

    // stage 0 prefetch
#pragma unroll
    for (int q = 0; q < 4; q++) {
        cp_async16(&As[0][lr * SSTR + lc + q * 8], &Ag[(size_t)lr * HH + lc + q * 8]);
        cp_async16(&Bs[0][lr * SSTR + lc + q * 8], &Bg[(size_t)lr * HH + lc + q * 8]);
    }
    asm volatile("cp.async.commit_group;");

    for (int k0 = 0; k0 < HH; k0 += KSTEP) {
        const int cur = (k0 / KSTEP) & 1;
        if (k0 + KSTEP < HH) {
            const int nxt = cur ^ 1;
            const int kn = k0 + KSTEP;
#pragma unroll
            for (int q = 0; q < 4; q++) {
                cp_async16(&As[nxt][lr * SSTR + lc + q * 8], &Ag[(size_t)lr * HH + kn + lc + q * 8]);
                cp_async16(&Bs[nxt][lr * SSTR + lc + q * 8], &Bg[(size_t)lr * HH + kn + lc + q * 8]);
            }
            asm volatile("cp.async.commit_group;");
            asm volatile("cp.async.wait_group 1;");
        } else {
            asm volatile("cp.async.wait_group 0;");
        }
        __syncthreads();

        const unsigned aBase = aSmem + (unsigned)cur * (STAGE_ELEMS * 2u) + laneA;
        const unsigned bBase = bSmem + (unsigned)cur * (STAGE_ELEMS * 2u) + laneB;

#pragma unroll
        for (int kk = 0; kk < KSTEP / 16; kk++) {
            unsigned a[4][4], b[4][2];
#pragma unroll
            for (int mi = 0; mi < 4; mi++)
                ldsm_x4(a[mi][0], a[mi][1], a[mi][2], a[mi][3],
                        aBase + (unsigned)(mi * 16 * SSTR + kk * 16) * 2u);
#pragma unroll
            for (int p = 0; p < 2; p++)
                ldsm_x4(b[2 * p][0], b[2 * p + 1][0], b[2 * p][1], b[2 * p + 1][1],
                        bBase + (unsigned)(p * 16 * SSTR + kk * 16) * 2u);
#pragma unroll
            for (int mi = 0; mi < 4; mi++)
#pragma unroll
                for (int ni = 0; ni < 4; ni++)
                    asm volatile(
                        "mma.sync.aligned.m16n8k16.row.col.f32.bf16.bf16.f32 "
                        "{%0,%1,%2,%3}, {%4,%5,%6,%7}, {%8,%9}, {%0,%1,%2,%3};"
                        : "+f"(c[mi][ni][0]), "+f"(c[mi][ni][1]),
                          "+f"(c[mi][ni][2]), "+f"(c[mi][ni][3])
                        : "r"(a[mi][0]), "r"(a[mi][1]), "r"(a[mi][2]), "r"(a[mi][3]),
                          "r"(b[ni][0]), "r"(b[ni][1]));
        }
        __syncthreads();
    }

#pragma unroll
    for (int mi = 0; mi < 4; mi++) {
        const int r0 = m0 + wm * 64 + mi * 16 + gid;
        const int r1 = r0 + 8;
        const float t0 = g_thr[r0], t1 = g_thr[r1];
#pragma unroll
        for (int ni = 0; ni < 4; ni++) {
            const int cb = n0 + wn * 32 + ni * 8 + qid * 2;
#pragma unroll
            for (int v = 0; v < 4; v++) {
                const int row = (v < 2) ? r0 : r1;
                const float t = (v < 2) ? t0 : t1;
                const int col = cb + (v & 1);
                if (c[mi][ni][v] >= t) {
                    int pos = atomicAdd(&g_cnt[row], 1);
                    if (pos < CAP) g_cidx[(size_t)row * CAP + pos] = col;
                }
            }
        }
    }
}

// ---------------- exact rescore: staged smem tiles -------------------------
#define RT 128
#define KC 64
#define WPAD 68
__global__ __launch_bounds__(256) void rescore_kernel(const float* __restrict__ hs) {
    const int row = blockIdx.x, tid = threadIdx.x;
    __shared__ float hsm[HH];
    __shared__ __align__(16) float ws[RT][WPAD];
    __shared__ int cidxs[RT];

    for (int i = tid; i < HH / 4; i += 256)
        ((float4*)hsm)[i] = ((const float4*)(hs + (size_t)row * HH))[i];

    int cnt = g_cnt[row];
    if (cnt > CAP) cnt = CAP;

    const int grp = tid >> 4, gj = tid & 15;

    for (int base = 0; base < cnt; base += RT) {
        const int tcnt = min(RT, cnt - base);
        __syncthreads();
        if (tid < tcnt) cidxs[tid] = g_cidx[(size_t)row * CAP + base + tid];
        __syncthreads();

        float acc = 0.f;
        for (int kc = 0; kc < HH; kc += KC) {
#pragma unroll
            for (int p = 0; p < RT / 16; p++) {
                const int r = p * 16 + grp;
                if (r < tcnt)
                    *(float4*)&ws[r][gj * 4] =
                        *(const float4*)(g_wtb + (size_t)cidxs[r] * HH + kc + gj * 4);
            }
            __syncthreads();
            if (tid < tcnt) {
                const float* w = ws[tid];
#pragma unroll
                for (int k = 0; k < KC; k++)
                    acc = __fmaf_rn(hsm[kc + k], w[k], acc);
            }
            __syncthreads();
        }
        if (tid < tcnt) {
            const int idx = cidxs[tid];
            const unsigned key = fkey(xla_tanh(xla_tanh(acc)));
            g_cand[(size_t)row * CAP + base + tid] =
                ((u64)key << 32) | (u64)(0xFFFFFFFFu - (unsigned)idx);
        }
    }
}

// ---------------- sort + completeness verification ------------------------
__global__ __launch_bounds__(256) void topk_kernel() {
    const int row = blockIdx.x, tid = threadIdx.x;
    const int cnt = g_cnt[row];

    if (cnt < KK || cnt > CAP) {
        if (tid == 0) g_flag[row] = 1;
        return;
    }

    __shared__ u64 skey[CAP];
    int n = 512;
    while (n < cnt) n <<= 1;
    const u64* src = g_cand + (size_t)row * CAP;
    for (int i = tid; i < n; i += 256) skey[i] = (i < cnt) ? src[i] : 0ull;
    __syncthreads();

    for (int ks = 2; ks <= n; ks <<= 1) {
        for (int j = ks >> 1; j > 0; j >>= 1) {
            for (int i = tid; i < n; i += 256) {
                int ixj = i ^ j;
                if (ixj > i) {
                    u64 a = skey[i], b = skey[ixj];
                    bool up = ((i & ks) == 0);
                    if (up ? (a < b) : (a > b)) { skey[i] = b; skey[ixj] = a; }
                }
            }
            __syncthreads();
        }
    }

    if ((unsigned)(skey[KK - 1] >> 32) <= g_keysafe[row]) {
        if (tid == 0) g_flag[row] = 1;
        return;
    }
    for (int i = tid; i < KK; i += 256) {
        unsigned low = (unsigned)(skey[i] & 0xFFFFFFFFu);
        g_topk[(size_t)row * KK + i] = (int)(0xFFFFFFFFu - low);
    }
}

// ---------------- fallback part 1: exact keys, coalesced ------------------
#define FBT 32
#define FBC (VV / FBT)
__global__ __launch_bounds__(256) void fb_scores(const float* __restrict__ hs) {
    const int row = blockIdx.y;
    if (!g_flag[row]) return;
    const int tid = threadIdx.x;
    const int col0 = blockIdx.x * FBC;

    __shared__ float hsm[HH];
    __shared__ __align__(16) float ws[RT][WPAD];
    for (int i = tid; i < HH / 4; i += 256)
        ((float4*)hsm)[i] = ((const float4*)(hs + (size_t)row * HH))[i];

    const int grp = tid >> 4, gj = tid & 15;
    for (int base = 0; base < FBC; base += RT) {
        const int tcnt = min(RT, FBC - base);
        __syncthreads();
        float acc = 0.f;
        for (int kc = 0; kc < HH; kc += KC) {
#pragma unroll
            for (int p = 0; p < RT / 16; p++) {
                const int r = p * 16 + grp;
                if (r < tcnt)
                    *(float4*)&ws[r][gj * 4] =
                        *(const float4*)(g_wtb + (size_t)(col0 + base + r) * HH + kc + gj * 4);
            }
            __syncthreads();
            if (tid < tcnt) {
                const float* w = ws[tid];
#pragma unroll
                for (int k = 0; k < KC; k++)
                    acc = __fmaf_rn(hsm[kc + k], w[k], acc);
            }
            __syncthreads();
        }
        if (tid < tcnt)
            g_keys[(size_t)row * VV + col0 + base + tid] =
                fkey(xla_tanh(xla_tanh(acc)));
    }
}

// ---------------- fallback part 2: radix select ---------------------------
__global__ __launch_bounds__(256) void fb_topk() {
    const int row = blockIdx.x, tid = threadIdx.x;
    if (!g_flag[row]) return;
    const unsigned* s = g_keys + (size_t)row * VV;

    __shared__ unsigned hist[256];
    __shared__ unsigned sh_prefix;
    __shared__ int sh_k, n_gt, n_eq;
    __shared__ int eq_idx[128];
    __shared__ u64 skey[512];
    if (tid == 0) { sh_prefix = 0u; sh_k = KK; }
    __syncthreads();
    for (int pass = 3; pass >= 0; --pass) {
        hist[tid] = 0;
        __syncthreads();
        const unsigned prefix = sh_prefix;
        const unsigned mask_hi = (pass == 3) ? 0u : (0xFFFFFFFFu << ((pass + 1) * 8));
        const int shift = pass * 8;
        for (int i = tid; i < VV; i += 256) {
            unsigned u = s[i];
            if ((u & mask_hi) == prefix)
                atomicAdd(&hist[(u >> shift) & 0xFFu], 1u);
        }
        __syncthreads();
        if (tid == 0) {
            int k = sh_k;
            unsigned cum = 0;
            for (int b = 255; b >= 0; --b) {
                cum += hist[b];
                if ((int)cum >= k) {
                    sh_k = k - (int)(cum - hist[b]);
                    sh_prefix = prefix | ((unsigned)b << shift);
                    break;
                }
            }
        }
        __syncthreads();
    }
    const unsigned P = sh_prefix;
    const int kneed = sh_k;
    if (tid == 0) { n_gt = 0; n_eq = 0; }
    __syncthreads();
    for (int i = tid; i < 512; i += 256) skey[i] = 0ull;
    __syncthreads();
    for (int i = tid; i < VV; i += 256) {
        unsigned u = s[i];
        if (u > P) {
            int p = atomicAdd(&n_gt, 1);
            skey[p] = ((u64)u << 32) | (u64)(0xFFFFFFFFu - (unsigned)i);
        } else if (u == P) {
            int p = atomicAdd(&n_eq, 1);
            if (p < 128) eq_idx[p] = i;
        }
    }
    __syncthreads();
    if (tid == 0) {
        int ne = n_eq; if (ne > 128) ne = 128;
        for (int a = 1; a < ne; a++) {
            int v = eq_idx[a]; int b = a - 1;
            while (b >= 0 && eq_idx[b] > v) { eq_idx[b + 1] = eq_idx[b]; --b; }
            eq_idx[b + 1] = v;
        }
        int take = kneed; if (take > ne) take = ne;
        for (int a = 0; a < take; a++)
            skey[n_gt + a] = ((u64)P << 32) | (u64)(0xFFFFFFFFu - (unsigned)eq_idx[a]);
    }
    __syncthreads();
    for (int ks = 2; ks <= 512; ks <<= 1) {
        for (int j = ks >> 1; j > 0; j >>= 1) {
            for (int i = tid; i < 512; i += 256) {
                int ixj = i ^ j;
                if (ixj > i) {
                    u64 a = skey[i], b = skey[ixj];
                    bool up = ((i & ks) == 0);
                    if (up ? (a < b) : (a > b)) { skey[i] = b; skey[ixj] = a; }
                }
            }
            __syncthreads();
        }
    }
    for (int i = tid; i < KK; i += 256) {
        unsigned low = (unsigned)(skey[i] & 0xFFFFFFFFu);
        g_topk[(size_t)row * KK + i] = (int)(0xFFFFFFFFu - low);
    }
}

// ---------------- gathered dot + scatter into sparse output --------------
__global__ __launch_bounds__(256) void scatter_kernel(
    const float* __restrict__ hs, float* __restrict__ out_logits,
    float* __restrict__ out_idx)
{
    const int row = blockIdx.x;
    __shared__ float4 h4[HH / 4];
    const int tid = threadIdx.x;
    for (int i = tid; i < HH / 4; i += 256)
        h4[i] = ((const float4*)(hs + (size_t)row * HH))[i];
    __syncthreads();

    const int warp = tid >> 5, lane = tid & 31;
    for (int c = warp; c < KK; c += 8) {
        int idx = g_topk[(size_t)row * KK + c];
        const float4* w4 = (const float4*)(g_wt + (size_t)idx * HH);
        float sum = 0.f;
#pragma unroll
        for (int t = lane; t < HH / 4; t += 32) {
            float4 a = h4[t], b = w4[t];
            sum = fmaf(a.x, b.x, sum);
            sum = fmaf(a.y, b.y, sum);
            sum = fmaf(a.z, b.z, sum);
            sum = fmaf(a.w, b.w, sum);
        }
#pragma unroll
        for (int o = 16; o > 0; o >>= 1) sum += __shfl_down_sync(0xFFFFFFFFu, sum, o);
        if (lane == 0) {
            out_logits[(size_t)row * VV + idx] = sum;
            out_idx[(size_t)row * KK + c] = (float)idx;
        }
    }
}

// ---------------- launch --------------------------------------------------
extern "C" void kernel_launch(void* const* d_in, const int* in_sizes, int n_in,
                              void* d_out, int out_size) {
    const float* hs    = (const float*)d_in[0];
    const float* w_out = (const float*)d_in[1];
    const float* w_bin = (const float*)d_in[2];
    float* out = (float*)d_out;

    const size_t logitsN = (size_t)MM * VV;
    size_t zeroN = logitsN;
    if ((size_t)out_size < zeroN) zeroN = (size_t)out_size;
    cudaMemsetAsync(d_out, 0, zeroN * sizeof(float), 0);

    void* p;
    cudaGetSymbolAddress(&p, g_cnt);
    cudaMemsetAsync(p, 0, MM * sizeof(int), 0);
    cudaGetSymbolAddress(&p, g_flag);
    cudaMemsetAsync(p, 0, MM * sizeof(int), 0);

    prep_kernel<<<MM, 256, 0, 0>>>(hs);
    transpose_wout<<<dim3(VV / 32, HH / 32), dim3(32, 8), 0, 0>>>(w_out);
    transpose_wbin<<<dim3(VV / 32, HH / 32), dim3(32, 8), 0, 0>>>(w_bin);
    mma_kernel<<<dim3(VV / 128, MM / 128), 256, 0, 0>>>();
    rescore_kernel<<<MM, 256, 0, 0>>>(hs);
    topk_kernel<<<MM, 256, 0, 0>>>();
    fb_scores<<<dim3(FBT, MM), 256, 0, 0>>>(hs);
    fb_topk<<<MM, 256, 0, 0>>>();
    scatter_kernel<<<MM, 256, 0, 0>>>(hs, out, out + logitsN);
}

// round 12
// speedup vs baseline: 1.0265x; 1.0265x over previous
#include <cuda_runtime.h>
#include <cuda_bf16.h>
#include <stdint.h>

typedef unsigned long long u64;
typedef unsigned short u16;

#define BB   2
#define SS   2048
#define MM   (BB * SS)
#define HH   512
#define VV   32000
#define KK   300
#define CAP  1024
#define T_CAND 2.20f
#define T_SAFE 2.26f

// ---------------- scratch (device globals) --------------------------------
__device__ unsigned g_keys[(size_t)MM * VV];
__device__ float    g_wt[(size_t)VV * HH];
__device__ float    g_wtb[(size_t)VV * HH];
__device__ __nv_bfloat16 a_bf[(size_t)MM * HH];
__device__ __nv_bfloat16 b_bf[(size_t)VV * HH];
__device__ int      g_topk[(size_t)MM * KK];
__device__ int      g_cidx[(size_t)MM * CAP];
__device__ u64      g_cand[(size_t)MM * CAP];
__device__ int      g_cnt[MM];
__device__ int      g_flag[MM];
__device__ float    g_thr[MM];
__device__ unsigned g_keysafe[MM];

// ---------------- XLA fast-tanh (BIT-EXACT — FROZEN) ----------------------
__device__ __forceinline__ float xla_tanh(float v) {
    float ax = fabsf(v);
    float x  = fminf(fmaxf(v, -7.99881172180175781f), 7.99881172180175781f);
    float x2 = __fmul_rn(x, x);
    float p = __fmaf_rn(x2, -2.76076847742355e-16f, 2.00018790482477e-13f);
    p = __fmaf_rn(x2, p, -8.60467152213735e-11f);
    p = __fmaf_rn(x2, p,  5.12229709037114e-08f);
    p = __fmaf_rn(x2, p,  1.48572235717979e-05f);
    p = __fmaf_rn(x2, p,  6.37261928875436e-04f);
    p = __fmaf_rn(x2, p,  4.89352455891786e-03f);
    p = __fmul_rn(x, p);
    float q = __fmaf_rn(x2, 1.19825839466702e-06f, 1.18534705686654e-04f);
    q = __fmaf_rn(x2, q, 2.26843463243900e-03f);
    q = __fmaf_rn(x2, q, 4.89352518554385e-03f);
    float r = __fdiv_rn(p, q);
    return (ax < 0.0004f) ? v : r;
}

__device__ __forceinline__ unsigned fkey(float f) {
    unsigned u = __float_as_uint(f);
    return (u & 0x80000000u) ? ~u : (u | 0x80000000u);
}

// ---------------- async copy / ldmatrix helpers ----------------------------
__device__ __forceinline__ void cp_async16(void* smem, const void* gmem) {
    unsigned s = (unsigned)__cvta_generic_to_shared(smem);
    asm volatile("cp.async.cg.shared.global [%0], [%1], 16;" :: "r"(s), "l"(gmem));
}
__device__ __forceinline__ void ldsm_x4(unsigned& r0, unsigned& r1,
                                        unsigned& r2, unsigned& r3, unsigned saddr) {
    asm volatile("ldmatrix.sync.aligned.m8n8.x4.shared.b16 {%0,%1,%2,%3}, [%4];"
        : "=r"(r0), "=r"(r1), "=r"(r2), "=r"(r3) : "r"(saddr));
}

// ---------------- row norms + bf16 convert + flag init ---------------------
__global__ __launch_bounds__(256) void prep_kernel(const float* __restrict__ hs) {
    const int row = blockIdx.x, tid = threadIdx.x;
    const float* h = hs + (size_t)row * HH;
    float v0 = h[tid], v1 = h[tid + 256];
    a_bf[(size_t)row * HH + tid]       = __float2bfloat16(v0);
    a_bf[(size_t)row * HH + tid + 256] = __float2bfloat16(v1);
    __shared__ float red[256];
    red[tid] = v0 * v0 + v1 * v1;
    __syncthreads();
    for (int o = 128; o > 0; o >>= 1) {
        if (tid < o) red[tid] += red[tid + o];
        __syncthreads();
    }
    if (tid == 0) {
        float s = sqrtf(red[0] / (float)HH);
        g_thr[row] = T_CAND * s;
        g_keysafe[row] = fkey(xla_tanh(xla_tanh(T_SAFE * s)));
        g_cnt[row] = 0;
        g_flag[row] = 0;
    }
}

// ---------------- transposes ----------------------------------------------
__global__ void transpose_wout(const float* __restrict__ W) {
    __shared__ float tile[32][33];
    int x = blockIdx.x * 32 + threadIdx.x;
    int y = blockIdx.y * 32 + threadIdx.y;
#pragma unroll
    for (int i = 0; i < 32; i += 8)
        tile[threadIdx.y + i][threadIdx.x] = W[(size_t)(y + i) * VV + x];
    __syncthreads();
    int xo = blockIdx.y * 32 + threadIdx.x;
    int yo = blockIdx.x * 32 + threadIdx.y;
#pragma unroll
    for (int i = 0; i < 32; i += 8)
        g_wt[(size_t)(yo + i) * HH + xo] = tile[threadIdx.x][threadIdx.y + i];
}

__global__ void transpose_wbin(const float* __restrict__ W) {
    __shared__ float tile[32][33];
    int x = blockIdx.x * 32 + threadIdx.x;
    int y = blockIdx.y * 32 + threadIdx.y;
#pragma unroll
    for (int i = 0; i < 32; i += 8)
        tile[threadIdx.y + i][threadIdx.x] = W[(size_t)(y + i) * VV + x];
    __syncthreads();
    int xo = blockIdx.y * 32 + threadIdx.x;
    int yo = blockIdx.x * 32 + threadIdx.y;
#pragma unroll
    for (int i = 0; i < 32; i += 8) {
        float v = tile[threadIdx.x][threadIdx.y + i];
        g_wtb[(size_t)(yo + i) * HH + xo] = v;
        b_bf[(size_t)(yo + i) * HH + xo]  = __float2bfloat16(v);
    }
}

// ---------------- bf16 mma GEMM: 3-stage cp.async ring, 1 barrier/stage ---
#define KSTEP 32
#define SSTR  40
#define MATE  (128 * SSTR)             // bf16 elems per matrix per stage
#define STAGE_ELEMS (2 * MATE)         // A + B
#define NST   (HH / KSTEP)             // 16
#define DYN_SMEM (3 * STAGE_ELEMS * 2) // 61440 bytes

__global__ __launch_bounds__(256) void mma_kernel() {
    extern __shared__ __align__(16) u16 smp[];

    const int tid  = threadIdx.x;
    const int warp = tid >> 5, lane = tid & 31;
    const int wm = warp & 1, wn = warp >> 1;
    const int gid = lane >> 2, qid = lane & 3;
    const int m0 = blockIdx.y * 128, n0 = blockIdx.x * 128;

    float c[4][4][4];
#pragma unroll
    for (int mi = 0; mi < 4; mi++)
#pragma unroll
        for (int ni = 0; ni < 4; ni++)
#pragma unroll
            for (int v = 0; v < 4; v++) c[mi][ni][v] = 0.f;

    const u16* Ag = (const u16*)a_bf + (size_t)m0 * HH;
    const u16* Bg = (const u16*)b_bf + (size_t)n0 * HH;
    const int lr = tid >> 1, lc = (tid & 1) * 16;

    const int lrow8 = ((lane >> 3) & 1) * 8 + (lane & 7);
    const int lcol8 = (lane >> 4) * 8;
    const unsigned smBase = (unsigned)__cvta_generic_to_shared(&smp[0]);
    const unsigned laneA = ((unsigned)((wm * 64 + lrow8) * SSTR + lcol8)) * 2u;
    const unsigned laneB = ((unsigned)((wn * 32 + lrow8) * SSTR + lcol8)) * 2u + (unsigned)(MATE * 2);

    auto load_stage = [&](int s) {
        u16* sb = smp + (s % 3) * STAGE_ELEMS;
        const int k0 = s * KSTEP;
        cp_async16(sb + lr * SSTR + lc,            Ag + (size_t)lr * HH + k0 + lc);
        cp_async16(sb + lr * SSTR + lc + 8,        Ag + (size_t)lr * HH + k0 + lc + 8);
        cp_async16(sb + MATE + lr * SSTR + lc,     Bg + (size_t)lr * HH + k0 + lc);
        cp_async16(sb + MATE + lr * SSTR + lc + 8, Bg + (size_t)lr * HH + k0 + lc + 8);
        asm volatile("cp.async.commit_group;");
    };

    load_stage(0);
    load_stage(1);

    for (int i = 0; i < NST; i++) {
        if (i + 2 < NST) asm volatile("cp.async.wait_group 1;");
        else             asm volatile("cp.async.wait_group 0;");
        __syncthreads();
        if (i + 2 < NST) load_stage(i + 2);

        const unsigned stOff = (unsigned)((i % 3) * STAGE_ELEMS * 2);
        const unsigned aBase = smBase + stOff + laneA;
        const unsigned bBase = smBase + stOff + laneB;

#pragma unroll
        for (int kk = 0; kk < KSTEP / 16; kk++) {
            unsigned a[4][4], b[4][2];
#pragma unroll
            for (int mi = 0; mi < 4; mi++)
                ldsm_x4(a[mi][0], a[mi][1], a[mi][2], a[mi][3],
                        aBase + (unsigned)(mi * 16 * SSTR + kk * 16) * 2u);
#pragma unroll
            for (int p = 0; p < 2; p++)
                ldsm_x4(b[2 * p][0], b[2 * p + 1][0], b[2 * p][1], b[2 * p + 1][1],
                        bBase + (unsigned)(p * 16 * SSTR + kk * 16) * 2u);
#pragma unroll
            for (int mi = 0; mi < 4; mi++)
#pragma unroll
                for (int ni = 0; ni < 4; ni++)
                    asm volatile(
                        "mma.sync.aligned.m16n8k16.row.col.f32.bf16.bf16.f32 "
                        "{%0,%1,%2,%3}, {%4,%5,%6,%7}, {%8,%9}, {%0,%1,%2,%3};"
                        : "+f"(c[mi][ni][0]), "+f"(c[mi][ni][1]),
                          "+f"(c[mi][ni][2]), "+f"(c[mi][ni][3])
                        : "r"(a[mi][0]), "r"(a[mi][1]), "r"(a[mi][2]), "r"(a[mi][3]),
                          "r"(b[ni][0]), "r"(b[ni][1]));
        }
    }

#pragma unroll
    for (int mi = 0; mi < 4; mi++) {
        const int r0 = m0 + wm * 64 + mi * 16 + gid;
        const int r1 = r0 + 8;
        const float t0 = g_thr[r0], t1 = g_thr[r1];
#pragma unroll
        for (int ni = 0; ni < 4; ni++) {
            const int cb = n0 + wn * 32 + ni * 8 + qid * 2;
#pragma unroll
            for (int v = 0; v < 4; v++) {
                const int row = (v < 2) ? r0 : r1;
                const float t = (v < 2) ? t0 : t1;
                const int col = cb + (v & 1);
                if (c[mi][ni][v] >= t) {
                    int pos = atomicAdd(&g_cnt[row], 1);
                    if (pos < CAP) g_cidx[(size_t)row * CAP + pos] = col;
                }
            }
        }
    }
}

// ---------------- exact rescore: staged smem tiles -------------------------
#define RT 128
#define KC 64
#define WPAD 68
__global__ __launch_bounds__(256) void rescore_kernel(const float* __restrict__ hs) {
    const int row = blockIdx.x, tid = threadIdx.x;
    __shared__ float hsm[HH];
    __shared__ __align__(16) float ws[RT][WPAD];
    __shared__ int cidxs[RT];

    for (int i = tid; i < HH / 4; i += 256)
        ((float4*)hsm)[i] = ((const float4*)(hs + (size_t)row * HH))[i];

    int cnt = g_cnt[row];
    if (cnt > CAP) cnt = CAP;

    const int grp = tid >> 4, gj = tid & 15;

    for (int base = 0; base < cnt; base += RT) {
        const int tcnt = min(RT, cnt - base);
        __syncthreads();
        if (tid < tcnt) cidxs[tid] = g_cidx[(size_t)row * CAP + base + tid];
        __syncthreads();

        float acc = 0.f;
        for (int kc = 0; kc < HH; kc += KC) {
#pragma unroll
            for (int p = 0; p < RT / 16; p++) {
                const int r = p * 16 + grp;
                if (r < tcnt)
                    *(float4*)&ws[r][gj * 4] =
                        *(const float4*)(g_wtb + (size_t)cidxs[r] * HH + kc + gj * 4);
            }
            __syncthreads();
            if (tid < tcnt) {
                const float* w = ws[tid];
#pragma unroll
                for (int k = 0; k < KC; k++)
                    acc = __fmaf_rn(hsm[kc + k], w[k], acc);
            }
            __syncthreads();
        }
        if (tid < tcnt) {
            const int idx = cidxs[tid];
            const unsigned key = fkey(xla_tanh(xla_tanh(acc)));
            g_cand[(size_t)row * CAP + base + tid] =
                ((u64)key << 32) | (u64)(0xFFFFFFFFu - (unsigned)idx);
        }
    }
}

// ---------------- sort + completeness verification ------------------------
__global__ __launch_bounds__(256) void topk_kernel() {
    const int row = blockIdx.x, tid = threadIdx.x;
    const int cnt = g_cnt[row];

    if (cnt < KK || cnt > CAP) {
        if (tid == 0) g_flag[row] = 1;
        return;
    }

    __shared__ u64 skey[CAP];
    int n = 512;
    while (n < cnt) n <<= 1;
    const u64* src = g_cand + (size_t)row * CAP;
    for (int i = tid; i < n; i += 256) skey[i] = (i < cnt) ? src[i] : 0ull;
    __syncthreads();

    for (int ks = 2; ks <= n; ks <<= 1) {
        for (int j = ks >> 1; j > 0; j >>= 1) {
            for (int i = tid; i < n; i += 256) {
                int ixj = i ^ j;
                if (ixj > i) {
                    u64 a = skey[i], b = skey[ixj];
                    bool up = ((i & ks) == 0);
                    if (up ? (a < b) : (a > b)) { skey[i] = b; skey[ixj] = a; }
                }
            }
            __syncthreads();
        }
    }

    if ((unsigned)(skey[KK - 1] >> 32) <= g_keysafe[row]) {
        if (tid == 0) g_flag[row] = 1;
        return;
    }
    for (int i = tid; i < KK; i += 256) {
        unsigned low = (unsigned)(skey[i] & 0xFFFFFFFFu);
        g_topk[(size_t)row * KK + i] = (int)(0xFFFFFFFFu - low);
    }
}

// ---------------- fallback part 1: exact keys, coalesced ------------------
#define FBT 32
#define FBC (VV / FBT)
__global__ __launch_bounds__(256) void fb_scores(const float* __restrict__ hs) {
    const int row = blockIdx.y;
    if (!g_flag[row]) return;
    const int tid = threadIdx.x;
    const int col0 = blockIdx.x * FBC;

    __shared__ float hsm[HH];
    __shared__ __align__(16) float ws[RT][WPAD];
    for (int i = tid; i < HH / 4; i += 256)
        ((float4*)hsm)[i] = ((const float4*)(hs + (size_t)row * HH))[i];

    const int grp = tid >> 4, gj = tid & 15;
    for (int base = 0; base < FBC; base += RT) {
        const int tcnt = min(RT, FBC - base);
        __syncthreads();
        float acc = 0.f;
        for (int kc = 0; kc < HH; kc += KC) {
#pragma unroll
            for (int p = 0; p < RT / 16; p++) {
                const int r = p * 16 + grp;
                if (r < tcnt)
                    *(float4*)&ws[r][gj * 4] =
                        *(const float4*)(g_wtb + (size_t)(col0 + base + r) * HH + kc + gj * 4);
            }
            __syncthreads();
            if (tid < tcnt) {
                const float* w = ws[tid];
#pragma unroll
                for (int k = 0; k < KC; k++)
                    acc = __fmaf_rn(hsm[kc + k], w[k], acc);
            }
            __syncthreads();
        }
        if (tid < tcnt)
            g_keys[(size_t)row * VV + col0 + base + tid] =
                fkey(xla_tanh(xla_tanh(acc)));
    }
}

// ---------------- fallback part 2: radix select ---------------------------
__global__ __launch_bounds__(256) void fb_topk() {
    const int row = blockIdx.x, tid = threadIdx.x;
    if (!g_flag[row]) return;
    const unsigned* s = g_keys + (size_t)row * VV;

    __shared__ unsigned hist[256];
    __shared__ unsigned sh_prefix;
    __shared__ int sh_k, n_gt, n_eq;
    __shared__ int eq_idx[128];
    __shared__ u64 skey[512];
    if (tid == 0) { sh_prefix = 0u; sh_k = KK; }
    __syncthreads();
    for (int pass = 3; pass >= 0; --pass) {
        hist[tid] = 0;
        __syncthreads();
        const unsigned prefix = sh_prefix;
        const unsigned mask_hi = (pass == 3) ? 0u : (0xFFFFFFFFu << ((pass + 1) * 8));
        const int shift = pass * 8;
        for (int i = tid; i < VV; i += 256) {
            unsigned u = s[i];
            if ((u & mask_hi) == prefix)
                atomicAdd(&hist[(u >> shift) & 0xFFu], 1u);
        }
        __syncthreads();
        if (tid == 0) {
            int k = sh_k;
            unsigned cum = 0;
            for (int b = 255; b >= 0; --b) {
                cum += hist[b];
                if ((int)cum >= k) {
                    sh_k = k - (int)(cum - hist[b]);
                    sh_prefix = prefix | ((unsigned)b << shift);
                    break;
                }
            }
        }
        __syncthreads();
    }
    const unsigned P = sh_prefix;
    const int kneed = sh_k;
    if (tid == 0) { n_gt = 0; n_eq = 0; }
    __syncthreads();
    for (int i = tid; i < 512; i += 256) skey[i] = 0ull;
    __syncthreads();
    for (int i = tid; i < VV; i += 256) {
        unsigned u = s[i];
        if (u > P) {
            int p = atomicAdd(&n_gt, 1);
            skey[p] = ((u64)u << 32) | (u64)(0xFFFFFFFFu - (unsigned)i);
        } else if (u == P) {
            int p = atomicAdd(&n_eq, 1);
            if (p < 128) eq_idx[p] = i;
        }
    }
    __syncthreads();
    if (tid == 0) {
        int ne = n_eq; if (ne > 128) ne = 128;
        for (int a = 1; a < ne; a++) {
            int v = eq_idx[a]; int b = a - 1;
            while (b >= 0 && eq_idx[b] > v) { eq_idx[b + 1] = eq_idx[b]; --b; }
            eq_idx[b + 1] = v;
        }
        int take = kneed; if (take > ne) take = ne;
        for (int a = 0; a < take; a++)
            skey[n_gt + a] = ((u64)P << 32) | (u64)(0xFFFFFFFFu - (unsigned)eq_idx[a]);
    }
    __syncthreads();
    for (int ks = 2; ks <= 512; ks <<= 1) {
        for (int j = ks >> 1; j > 0; j >>= 1) {
            for (int i = tid; i < 512; i += 256) {
                int ixj = i ^ j;
                if (ixj > i) {
                    u64 a = skey[i], b = skey[ixj];
                    bool up = ((i & ks) == 0);
                    if (up ? (a < b) : (a > b)) { skey[i] = b; skey[ixj] = a; }
                }
            }
            __syncthreads();
        }
    }
    for (int i = tid; i < KK; i += 256) {
        unsigned low = (unsigned)(skey[i] & 0xFFFFFFFFu);
        g_topk[(size_t)row * KK + i] = (int)(0xFFFFFFFFu - low);
    }
}

// ---------------- fused zero + gathered dot + scatter ----------------------
__global__ __launch_bounds__(256) void scatter_kernel(
    const float* __restrict__ hs, float* __restrict__ out_logits,
    float* __restrict__ out_idx)
{
    const int row = blockIdx.x;
    const int tid = threadIdx.x;
    __shared__ float4 h4[HH / 4];
    for (int i = tid; i < HH / 4; i += 256)
        h4[i] = ((const float4*)(hs + (size_t)row * HH))[i];

    // zero this row of the sparse output (poisoned by harness)
    float4* orow4 = (float4*)(out_logits + (size_t)row * VV);
    const float4 z4 = make_float4(0.f, 0.f, 0.f, 0.f);
    for (int i = tid; i < VV / 4; i += 256) orow4[i] = z4;
    __syncthreads();

    const int warp = tid >> 5, lane = tid & 31;
    for (int c = warp; c < KK; c += 8) {
        int idx = g_topk[(size_t)row * KK + c];
        const float4* w4 = (const float4*)(g_wt + (size_t)idx * HH);
        float sum = 0.f;
#pragma unroll
        for (int t = lane; t < HH / 4; t += 32) {
            float4 a = h4[t], b = w4[t];
            sum = fmaf(a.x, b.x, sum);
            sum = fmaf(a.y, b.y, sum);
            sum = fmaf(a.z, b.z, sum);
            sum = fmaf(a.w, b.w, sum);
        }
#pragma unroll
        for (int o = 16; o > 0; o >>= 1) sum += __shfl_down_sync(0xFFFFFFFFu, sum, o);
        if (lane == 0) {
            out_logits[(size_t)row * VV + idx] = sum;
            out_idx[(size_t)row * KK + c] = (float)idx;
        }
    }
}

// ---------------- launch --------------------------------------------------
extern "C" void kernel_launch(void* const* d_in, const int* in_sizes, int n_in,
                              void* d_out, int out_size) {
    const float* hs    = (const float*)d_in[0];
    const float* w_out = (const float*)d_in[1];
    const float* w_bin = (const float*)d_in[2];
    float* out = (float*)d_out;

    cudaFuncSetAttribute(mma_kernel,
                         cudaFuncAttributeMaxDynamicSharedMemorySize, DYN_SMEM);

    const size_t logitsN = (size_t)MM * VV;

    prep_kernel<<<MM, 256, 0, 0>>>(hs);
    transpose_wout<<<dim3(VV / 32, HH / 32), dim3(32, 8), 0, 0>>>(w_out);
    transpose_wbin<<<dim3(VV / 32, HH / 32), dim3(32, 8), 0, 0>>>(w_bin);
    mma_kernel<<<dim3(VV / 128, MM / 128), 256, DYN_SMEM, 0>>>();
    rescore_kernel<<<MM, 256, 0, 0>>>(hs);
    topk_kernel<<<MM, 256, 0, 0>>>();
    fb_scores<<<dim3(FBT, MM), 256, 0, 0>>>(hs);
    fb_topk<<<MM, 256, 0, 0>>>();
    scatter_kernel<<<MM, 256, 0, 0>>>(hs, out, out + logitsN);
}

// round 13
// speedup vs baseline: 1.0414x; 1.0146x over previous
#include <cuda_runtime.h>
#include <cuda_bf16.h>
#include <stdint.h>

typedef unsigned long long u64;
typedef unsigned short u16;

#define BB   2
#define SS   2048
#define MM   (BB * SS)
#define HH   512
#define VV   32000
#define KK   300
#define CAP  1024
#define T_CAND 2.20f
#define T_SAFE 2.26f

// ---------------- scratch (device globals) --------------------------------
__device__ unsigned g_keys[(size_t)MM * VV];
__device__ float    g_wt[(size_t)VV * HH];
__device__ float    g_wtb[(size_t)VV * HH];
__device__ __nv_bfloat16 a_bf[(size_t)MM * HH];
__device__ __nv_bfloat16 b_bf[(size_t)VV * HH];
__device__ int      g_topk[(size_t)MM * KK];
__device__ int      g_cidx[(size_t)MM * CAP];
__device__ u64      g_cand[(size_t)MM * CAP];
__device__ int      g_cnt[MM];
__device__ int      g_flag[MM];
__device__ float    g_thr[MM];
__device__ unsigned g_keysafe[MM];

// ---------------- XLA fast-tanh (BIT-EXACT — FROZEN) ----------------------
__device__ __forceinline__ float xla_tanh(float v) {
    float ax = fabsf(v);
    float x  = fminf(fmaxf(v, -7.99881172180175781f), 7.99881172180175781f);
    float x2 = __fmul_rn(x, x);
    float p = __fmaf_rn(x2, -2.76076847742355e-16f, 2.00018790482477e-13f);
    p = __fmaf_rn(x2, p, -8.60467152213735e-11f);
    p = __fmaf_rn(x2, p,  5.12229709037114e-08f);
    p = __fmaf_rn(x2, p,  1.48572235717979e-05f);
    p = __fmaf_rn(x2, p,  6.37261928875436e-04f);
    p = __fmaf_rn(x2, p,  4.89352455891786e-03f);
    p = __fmul_rn(x, p);
    float q = __fmaf_rn(x2, 1.19825839466702e-06f, 1.18534705686654e-04f);
    q = __fmaf_rn(x2, q, 2.26843463243900e-03f);
    q = __fmaf_rn(x2, q, 4.89352518554385e-03f);
    float r = __fdiv_rn(p, q);
    return (ax < 0.0004f) ? v : r;
}

__device__ __forceinline__ unsigned fkey(float f) {
    unsigned u = __float_as_uint(f);
    return (u & 0x80000000u) ? ~u : (u | 0x80000000u);
}

// ---------------- async copy / ldmatrix helpers ----------------------------
__device__ __forceinline__ void cp_async16(void* smem, const void* gmem) {
    unsigned s = (unsigned)__cvta_generic_to_shared(smem);
    asm volatile("cp.async.cg.shared.global [%0], [%1], 16;" :: "r"(s), "l"(gmem));
}
__device__ __forceinline__ void ldsm_x4(unsigned& r0, unsigned& r1,
                                        unsigned& r2, unsigned& r3, unsigned saddr) {
    asm volatile("ldmatrix.sync.aligned.m8n8.x4.shared.b16 {%0,%1,%2,%3}, [%4];"
        : "=r"(r0), "=r"(r1), "=r"(r2), "=r"(r3) : "r"(saddr));
}

// ---------------- row norms + bf16 convert + flag init ---------------------
__global__ __launch_bounds__(256) void prep_kernel(const float* __restrict__ hs) {
    const int row = blockIdx.x, tid = threadIdx.x;
    const float* h = hs + (size_t)row * HH;
    float v0 = h[tid], v1 = h[tid + 256];
    a_bf[(size_t)row * HH + tid]       = __float2bfloat16(v0);
    a_bf[(size_t)row * HH + tid + 256] = __float2bfloat16(v1);
    __shared__ float red[256];
    red[tid] = v0 * v0 + v1 * v1;
    __syncthreads();
    for (int o = 128; o > 0; o >>= 1) {
        if (tid < o) red[tid] += red[tid + o];
        __syncthreads();
    }
    if (tid == 0) {
        float s = sqrtf(red[0] / (float)HH);
        g_thr[row] = T_CAND * s;
        g_keysafe[row] = fkey(xla_tanh(xla_tanh(T_SAFE * s)));
        g_cnt[row] = 0;
        g_flag[row] = 0;
    }
}

// ---------------- transposes ----------------------------------------------
__global__ void transpose_wout(const float* __restrict__ W) {
    __shared__ float tile[32][33];
    int x = blockIdx.x * 32 + threadIdx.x;
    int y = blockIdx.y * 32 + threadIdx.y;
#pragma unroll
    for (int i = 0; i < 32; i += 8)
        tile[threadIdx.y + i][threadIdx.x] = W[(size_t)(y + i) * VV + x];
    __syncthreads();
    int xo = blockIdx.y * 32 + threadIdx.x;
    int yo = blockIdx.x * 32 + threadIdx.y;
#pragma unroll
    for (int i = 0; i < 32; i += 8)
        g_wt[(size_t)(yo + i) * HH + xo] = tile[threadIdx.x][threadIdx.y + i];
}

__global__ void transpose_wbin(const float* __restrict__ W) {
    __shared__ float tile[32][33];
    int x = blockIdx.x * 32 + threadIdx.x;
    int y = blockIdx.y * 32 + threadIdx.y;
#pragma unroll
    for (int i = 0; i < 32; i += 8)
        tile[threadIdx.y + i][threadIdx.x] = W[(size_t)(y + i) * VV + x];
    __syncthreads();
    int xo = blockIdx.y * 32 + threadIdx.x;
    int yo = blockIdx.x * 32 + threadIdx.y;
#pragma unroll
    for (int i = 0; i < 32; i += 8) {
        float v = tile[threadIdx.x][threadIdx.y + i];
        g_wtb[(size_t)(yo + i) * HH + xo] = v;
        b_bf[(size_t)(yo + i) * HH + xo]  = __float2bfloat16(v);
    }
}

// ---------------- bf16 mma GEMM: 3-stage ring + fragment ping-pong --------
#define KSTEP 32
#define SSTR  40
#define MATE  (128 * SSTR)
#define STAGE_ELEMS (2 * MATE)
#define NST   (HH / KSTEP)             // 16
#define DYN_SMEM (3 * STAGE_ELEMS * 2) // 61440 bytes

__global__ __launch_bounds__(256, 2) void mma_kernel() {
    extern __shared__ __align__(16) u16 smp[];

    const int tid  = threadIdx.x;
    const int warp = tid >> 5, lane = tid & 31;
    const int wm = warp & 1, wn = warp >> 1;
    const int gid = lane >> 2, qid = lane & 3;
    const int m0 = blockIdx.y * 128, n0 = blockIdx.x * 128;

    float c[4][4][4];
#pragma unroll
    for (int mi = 0; mi < 4; mi++)
#pragma unroll
        for (int ni = 0; ni < 4; ni++)
#pragma unroll
            for (int v = 0; v < 4; v++) c[mi][ni][v] = 0.f;

    const u16* Ag = (const u16*)a_bf + (size_t)m0 * HH;
    const u16* Bg = (const u16*)b_bf + (size_t)n0 * HH;
    const int lr = tid >> 1, lc = (tid & 1) * 16;

    const int lrow8 = ((lane >> 3) & 1) * 8 + (lane & 7);
    const int lcol8 = (lane >> 4) * 8;
    const unsigned smBase = (unsigned)__cvta_generic_to_shared(&smp[0]);
    const unsigned laneA = ((unsigned)((wm * 64 + lrow8) * SSTR + lcol8)) * 2u;
    const unsigned laneB = ((unsigned)((wn * 32 + lrow8) * SSTR + lcol8)) * 2u + (unsigned)(MATE * 2);

    auto load_stage = [&](int s) {
        u16* sb = smp + (s % 3) * STAGE_ELEMS;
        const int k0 = s * KSTEP;
        cp_async16(sb + lr * SSTR + lc,            Ag + (size_t)lr * HH + k0 + lc);
        cp_async16(sb + lr * SSTR + lc + 8,        Ag + (size_t)lr * HH + k0 + lc + 8);
        cp_async16(sb + MATE + lr * SSTR + lc,     Bg + (size_t)lr * HH + k0 + lc);
        cp_async16(sb + MATE + lr * SSTR + lc + 8, Bg + (size_t)lr * HH + k0 + lc + 8);
        asm volatile("cp.async.commit_group;");
    };

    // ping-pong fragment sets
    unsigned aF[2][4][4], bF[2][4][2];

    auto ldfrags = [&](int set, unsigned stOff, int kk) {
        const unsigned aBase = smBase + stOff + laneA + (unsigned)(kk * 16) * 2u;
        const unsigned bBase = smBase + stOff + laneB + (unsigned)(kk * 16) * 2u;
#pragma unroll
        for (int mi = 0; mi < 4; mi++)
            ldsm_x4(aF[set][mi][0], aF[set][mi][1], aF[set][mi][2], aF[set][mi][3],
                    aBase + (unsigned)(mi * 16 * SSTR) * 2u);
#pragma unroll
        for (int p = 0; p < 2; p++)
            ldsm_x4(bF[set][2 * p][0], bF[set][2 * p + 1][0],
                    bF[set][2 * p][1], bF[set][2 * p + 1][1],
                    bBase + (unsigned)(p * 16 * SSTR) * 2u);
    };

    auto compute = [&](int set) {
#pragma unroll
        for (int mi = 0; mi < 4; mi++)
#pragma unroll
            for (int ni = 0; ni < 4; ni++)
                asm volatile(
                    "mma.sync.aligned.m16n8k16.row.col.f32.bf16.bf16.f32 "
                    "{%0,%1,%2,%3}, {%4,%5,%6,%7}, {%8,%9}, {%0,%1,%2,%3};"
                    : "+f"(c[mi][ni][0]), "+f"(c[mi][ni][1]),
                      "+f"(c[mi][ni][2]), "+f"(c[mi][ni][3])
                    : "r"(aF[set][mi][0]), "r"(aF[set][mi][1]),
                      "r"(aF[set][mi][2]), "r"(aF[set][mi][3]),
                      "r"(bF[set][ni][0]), "r"(bF[set][ni][1]));
    };

    load_stage(0);
    load_stage(1);
    asm volatile("cp.async.wait_group 1;");
    __syncthreads();
    ldfrags(0, 0u, 0);   // stage 0, kk0

    for (int i = 0; i < NST; i++) {
        const unsigned so = (unsigned)((i % 3) * STAGE_ELEMS * 2);
        ldfrags(1, so, 1);           // prefetch kk1 of this stage
        compute(0);                  // kk0 (LDSM kk1 in flight)
        if (i + 1 < NST) {
            if (i + 2 < NST) {
                load_stage(i + 2);
                asm volatile("cp.async.wait_group 1;");
            } else {
                asm volatile("cp.async.wait_group 0;");
            }
            __syncthreads();         // stage i+1 smem ready; buf (i+2)%3 free
            ldfrags(0, (unsigned)(((i + 1) % 3) * STAGE_ELEMS * 2), 0); // prefetch next kk0
            compute(1);              // kk1 (next-stage LDSM in flight)
        } else {
            compute(1);
        }
    }

#pragma unroll
    for (int mi = 0; mi < 4; mi++) {
        const int r0 = m0 + wm * 64 + mi * 16 + gid;
        const int r1 = r0 + 8;
        const float t0 = g_thr[r0], t1 = g_thr[r1];
#pragma unroll
        for (int ni = 0; ni < 4; ni++) {
            const int cb = n0 + wn * 32 + ni * 8 + qid * 2;
#pragma unroll
            for (int v = 0; v < 4; v++) {
                const int row = (v < 2) ? r0 : r1;
                const float t = (v < 2) ? t0 : t1;
                const int col = cb + (v & 1);
                if (c[mi][ni][v] >= t) {
                    int pos = atomicAdd(&g_cnt[row], 1);
                    if (pos < CAP) g_cidx[(size_t)row * CAP + pos] = col;
                }
            }
        }
    }
}

// ---------------- exact rescore: staged smem tiles -------------------------
#define RT 128
#define KC 64
#define WPAD 68
__global__ __launch_bounds__(256) void rescore_kernel(const float* __restrict__ hs) {
    const int row = blockIdx.x, tid = threadIdx.x;
    __shared__ float hsm[HH];
    __shared__ __align__(16) float ws[RT][WPAD];
    __shared__ int cidxs[RT];

    for (int i = tid; i < HH / 4; i += 256)
        ((float4*)hsm)[i] = ((const float4*)(hs + (size_t)row * HH))[i];

    int cnt = g_cnt[row];
    if (cnt > CAP) cnt = CAP;

    const int grp = tid >> 4, gj = tid & 15;

    for (int base = 0; base < cnt; base += RT) {
        const int tcnt = min(RT, cnt - base);
        __syncthreads();
        if (tid < tcnt) cidxs[tid] = g_cidx[(size_t)row * CAP + base + tid];
        __syncthreads();

        float acc = 0.f;
        for (int kc = 0; kc < HH; kc += KC) {
#pragma unroll
            for (int p = 0; p < RT / 16; p++) {
                const int r = p * 16 + grp;
                if (r < tcnt)
                    *(float4*)&ws[r][gj * 4] =
                        *(const float4*)(g_wtb + (size_t)cidxs[r] * HH + kc + gj * 4);
            }
            __syncthreads();
            if (tid < tcnt) {
                const float* w = ws[tid];
#pragma unroll
                for (int k = 0; k < KC; k++)
                    acc = __fmaf_rn(hsm[kc + k], w[k], acc);
            }
            __syncthreads();
        }
        if (tid < tcnt) {
            const int idx = cidxs[tid];
            const unsigned key = fkey(xla_tanh(xla_tanh(acc)));
            g_cand[(size_t)row * CAP + base + tid] =
                ((u64)key << 32) | (u64)(0xFFFFFFFFu - (unsigned)idx);
        }
    }
}

// ---------------- sort + completeness verification ------------------------
__global__ __launch_bounds__(256) void topk_kernel() {
    const int row = blockIdx.x, tid = threadIdx.x;
    const int cnt = g_cnt[row];

    if (cnt < KK || cnt > CAP) {
        if (tid == 0) g_flag[row] = 1;
        return;
    }

    __shared__ u64 skey[CAP];
    int n = 512;
    while (n < cnt) n <<= 1;
    const u64* src = g_cand + (size_t)row * CAP;
    for (int i = tid; i < n; i += 256) skey[i] = (i < cnt) ? src[i] : 0ull;
    __syncthreads();

    for (int ks = 2; ks <= n; ks <<= 1) {
        for (int j = ks >> 1; j > 0; j >>= 1) {
            for (int i = tid; i < n; i += 256) {
                int ixj = i ^ j;
                if (ixj > i) {
                    u64 a = skey[i], b = skey[ixj];
                    bool up = ((i & ks) == 0);
                    if (up ? (a < b) : (a > b)) { skey[i] = b; skey[ixj] = a; }
                }
            }
            __syncthreads();
        }
    }

    if ((unsigned)(skey[KK - 1] >> 32) <= g_keysafe[row]) {
        if (tid == 0) g_flag[row] = 1;
        return;
    }
    for (int i = tid; i < KK; i += 256) {
        unsigned low = (unsigned)(skey[i] & 0xFFFFFFFFu);
        g_topk[(size_t)row * KK + i] = (int)(0xFFFFFFFFu - low);
    }
}

// ---------------- fallback part 1: exact keys, coalesced ------------------
#define FBT 32
#define FBC (VV / FBT)
__global__ __launch_bounds__(256) void fb_scores(const float* __restrict__ hs) {
    const int row = blockIdx.y;
    if (!g_flag[row]) return;
    const int tid = threadIdx.x;
    const int col0 = blockIdx.x * FBC;

    __shared__ float hsm[HH];
    __shared__ __align__(16) float ws[RT][WPAD];
    for (int i = tid; i < HH / 4; i += 256)
        ((float4*)hsm)[i] = ((const float4*)(hs + (size_t)row * HH))[i];

    const int grp = tid >> 4, gj = tid & 15;
    for (int base = 0; base < FBC; base += RT) {
        const int tcnt = min(RT, FBC - base);
        __syncthreads();
        float acc = 0.f;
        for (int kc = 0; kc < HH; kc += KC) {
#pragma unroll
            for (int p = 0; p < RT / 16; p++) {
                const int r = p * 16 + grp;
                if (r < tcnt)
                    *(float4*)&ws[r][gj * 4] =
                        *(const float4*)(g_wtb + (size_t)(col0 + base + r) * HH + kc + gj * 4);
            }
            __syncthreads();
            if (tid < tcnt) {
                const float* w = ws[tid];
#pragma unroll
                for (int k = 0; k < KC; k++)
                    acc = __fmaf_rn(hsm[kc + k], w[k], acc);
            }
            __syncthreads();
        }
        if (tid < tcnt)
            g_keys[(size_t)row * VV + col0 + base + tid] =
                fkey(xla_tanh(xla_tanh(acc)));
    }
}

// ---------------- fallback part 2: radix select ---------------------------
__global__ __launch_bounds__(256) void fb_topk() {
    const int row = blockIdx.x, tid = threadIdx.x;
    if (!g_flag[row]) return;
    const unsigned* s = g_keys + (size_t)row * VV;

    __shared__ unsigned hist[256];
    __shared__ unsigned sh_prefix;
    __shared__ int sh_k, n_gt, n_eq;
    __shared__ int eq_idx[128];
    __shared__ u64 skey[512];
    if (tid == 0) { sh_prefix = 0u; sh_k = KK; }
    __syncthreads();
    for (int pass = 3; pass >= 0; --pass) {
        hist[tid] = 0;
        __syncthreads();
        const unsigned prefix = sh_prefix;
        const unsigned mask_hi = (pass == 3) ? 0u : (0xFFFFFFFFu << ((pass + 1) * 8));
        const int shift = pass * 8;
        for (int i = tid; i < VV; i += 256) {
            unsigned u = s[i];
            if ((u & mask_hi) == prefix)
                atomicAdd(&hist[(u >> shift) & 0xFFu], 1u);
        }
        __syncthreads();
        if (tid == 0) {
            int k = sh_k;
            unsigned cum = 0;
            for (int b = 255; b >= 0; --b) {
                cum += hist[b];
                if ((int)cum >= k) {
                    sh_k = k - (int)(cum - hist[b]);
                    sh_prefix = prefix | ((unsigned)b << shift);
                    break;
                }
            }
        }
        __syncthreads();
    }
    const unsigned P = sh_prefix;
    const int kneed = sh_k;
    if (tid == 0) { n_gt = 0; n_eq = 0; }
    __syncthreads();
    for (int i = tid; i < 512; i += 256) skey[i] = 0ull;
    __syncthreads();
    for (int i = tid; i < VV; i += 256) {
        unsigned u = s[i];
        if (u > P) {
            int p = atomicAdd(&n_gt, 1);
            skey[p] = ((u64)u << 32) | (u64)(0xFFFFFFFFu - (unsigned)i);
        } else if (u == P) {
            int p = atomicAdd(&n_eq, 1);
            if (p < 128) eq_idx[p] = i;
        }
    }
    __syncthreads();
    if (tid == 0) {
        int ne = n_eq; if (ne > 128) ne = 128;
        for (int a = 1; a < ne; a++) {
            int v = eq_idx[a]; int b = a - 1;
            while (b >= 0 && eq_idx[b] > v) { eq_idx[b + 1] = eq_idx[b]; --b; }
            eq_idx[b + 1] = v;
        }
        int take = kneed; if (take > ne) take = ne;
        for (int a = 0; a < take; a++)
            skey[n_gt + a] = ((u64)P << 32) | (u64)(0xFFFFFFFFu - (unsigned)eq_idx[a]);
    }
    __syncthreads();
    for (int ks = 2; ks <= 512; ks <<= 1) {
        for (int j = ks >> 1; j > 0; j >>= 1) {
            for (int i = tid; i < 512; i += 256) {
                int ixj = i ^ j;
                if (ixj > i) {
                    u64 a = skey[i], b = skey[ixj];
                    bool up = ((i & ks) == 0);
                    if (up ? (a < b) : (a > b)) { skey[i] = b; skey[ixj] = a; }
                }
            }
            __syncthreads();
        }
    }
    for (int i = tid; i < KK; i += 256) {
        unsigned low = (unsigned)(skey[i] & 0xFFFFFFFFu);
        g_topk[(size_t)row * KK + i] = (int)(0xFFFFFFFFu - low);
    }
}

// ---------------- fused zero + gathered dot + scatter ----------------------
__global__ __launch_bounds__(256) void scatter_kernel(
    const float* __restrict__ hs, float* __restrict__ out_logits,
    float* __restrict__ out_idx)
{
    const int row = blockIdx.x;
    const int tid = threadIdx.x;
    __shared__ float4 h4[HH / 4];
    for (int i = tid; i < HH / 4; i += 256)
        h4[i] = ((const float4*)(hs + (size_t)row * HH))[i];

    float4* orow4 = (float4*)(out_logits + (size_t)row * VV);
    const float4 z4 = make_float4(0.f, 0.f, 0.f, 0.f);
    for (int i = tid; i < VV / 4; i += 256) orow4[i] = z4;
    __syncthreads();

    const int warp = tid >> 5, lane = tid & 31;
    for (int c = warp; c < KK; c += 8) {
        int idx = g_topk[(size_t)row * KK + c];
        const float4* w4 = (const float4*)(g_wt + (size_t)idx * HH);
        float sum = 0.f;
#pragma unroll
        for (int t = lane; t < HH / 4; t += 32) {
            float4 a = h4[t], b = w4[t];
            sum = fmaf(a.x, b.x, sum);
            sum = fmaf(a.y, b.y, sum);
            sum = fmaf(a.z, b.z, sum);
            sum = fmaf(a.w, b.w, sum);
        }
#pragma unroll
        for (int o = 16; o > 0; o >>= 1) sum += __shfl_down_sync(0xFFFFFFFFu, sum, o);
        if (lane == 0) {
            out_logits[(size_t)row * VV + idx] = sum;
            out_idx[(size_t)row * KK + c] = (float)idx;
        }
    }
}

// ---------------- launch --------------------------------------------------
extern "C" void kernel_launch(void* const* d_in, const int* in_sizes, int n_in,
                              void* d_out, int out_size) {
    const float* hs    = (const float*)d_in[0];
    const float* w_out = (const float*)d_in[1];
    const float* w_bin = (const float*)d_in[2];
    float* out = (float*)d_out;

    cudaFuncSetAttribute(mma_kernel,
                         cudaFuncAttributeMaxDynamicSharedMemorySize, DYN_SMEM);

    const size_t logitsN = (size_t)MM * VV;

    prep_kernel<<<MM, 256, 0, 0>>>(hs);
    transpose_wout<<<dim3(VV / 32, HH / 32), dim3(32, 8), 0, 0>>>(w_out);
    transpose_wbin<<<dim3(VV / 32, HH / 32), dim3(32, 8), 0, 0>>>(w_bin);
    mma_kernel<<<dim3(VV / 128, MM / 128), 256, DYN_SMEM, 0>>>();
    rescore_kernel<<<MM, 256, 0, 0>>>(hs);
    topk_kernel<<<MM, 256, 0, 0>>>();
    fb_scores<<<dim3(FBT, MM), 256, 0, 0>>>(hs);
    fb_topk<<<MM, 256, 0, 0>>>();
    scatter_kernel<<<MM, 256, 0, 0>>>(hs, out, out + logitsN);
}

// round 14
// speedup vs baseline: 1.0554x; 1.0134x over previous
#include <cuda_runtime.h>
#include <cuda_bf16.h>
#include <stdint.h>

typedef unsigned long long u64;
typedef unsigned short u16;

#define BB   2
#define SS   2048
#define MM   (BB * SS)
#define HH   512
#define VV   32000
#define KK   300
#define CAP  1024
#define T_CAND 2.20f
#define T_SAFE 2.26f

// ---------------- scratch (device globals) --------------------------------
__device__ unsigned g_keys[(size_t)MM * VV];
__device__ float    g_wt[(size_t)VV * HH];
__device__ float    g_wtb[(size_t)VV * HH];
__device__ __nv_bfloat16 a_bf[(size_t)MM * HH];
__device__ __nv_bfloat16 b_bf[(size_t)VV * HH];
__device__ int      g_topk[(size_t)MM * KK];
__device__ int      g_cidx[(size_t)MM * CAP];
__device__ u64      g_cand[(size_t)MM * CAP];
__device__ int      g_cnt[MM];
__device__ int      g_flag[MM];
__device__ float    g_thr[MM];
__device__ unsigned g_keysafe[MM];

// ---------------- XLA fast-tanh (BIT-EXACT — FROZEN) ----------------------
__device__ __forceinline__ float xla_tanh(float v) {
    float ax = fabsf(v);
    float x  = fminf(fmaxf(v, -7.99881172180175781f), 7.99881172180175781f);
    float x2 = __fmul_rn(x, x);
    float p = __fmaf_rn(x2, -2.76076847742355e-16f, 2.00018790482477e-13f);
    p = __fmaf_rn(x2, p, -8.60467152213735e-11f);
    p = __fmaf_rn(x2, p,  5.12229709037114e-08f);
    p = __fmaf_rn(x2, p,  1.48572235717979e-05f);
    p = __fmaf_rn(x2, p,  6.37261928875436e-04f);
    p = __fmaf_rn(x2, p,  4.89352455891786e-03f);
    p = __fmul_rn(x, p);
    float q = __fmaf_rn(x2, 1.19825839466702e-06f, 1.18534705686654e-04f);
    q = __fmaf_rn(x2, q, 2.26843463243900e-03f);
    q = __fmaf_rn(x2, q, 4.89352518554385e-03f);
    float r = __fdiv_rn(p, q);
    return (ax < 0.0004f) ? v : r;
}

__device__ __forceinline__ unsigned fkey(float f) {
    unsigned u = __float_as_uint(f);
    return (u & 0x80000000u) ? ~u : (u | 0x80000000u);
}

// ---------------- async copy / ldmatrix helpers ----------------------------
__device__ __forceinline__ void cp_async16(void* smem, const void* gmem) {
    unsigned s = (unsigned)__cvta_generic_to_shared(smem);
    asm volatile("cp.async.cg.shared.global [%0], [%1], 16;" :: "r"(s), "l"(gmem));
}
__device__ __forceinline__ void ldsm_x4(unsigned& r0, unsigned& r1,
                                        unsigned& r2, unsigned& r3, unsigned saddr) {
    asm volatile("ldmatrix.sync.aligned.m8n8.x4.shared.b16 {%0,%1,%2,%3}, [%4];"
        : "=r"(r0), "=r"(r1), "=r"(r2), "=r"(r3) : "r"(saddr));
}

// ---------------- row norms + bf16 convert + flag init ---------------------
__global__ __launch_bounds__(256) void prep_kernel(const float* __restrict__ hs) {
    const int row = blockIdx.x, tid = threadIdx.x;
    const float* h = hs + (size_t)row * HH;
    float v0 = h[tid], v1 = h[tid + 256];
    a_bf[(size_t)row * HH + tid]       = __float2bfloat16(v0);
    a_bf[(size_t)row * HH + tid + 256] = __float2bfloat16(v1);
    __shared__ float red[256];
    red[tid] = v0 * v0 + v1 * v1;
    __syncthreads();
    for (int o = 128; o > 0; o >>= 1) {
        if (tid < o) red[tid] += red[tid + o];
        __syncthreads();
    }
    if (tid == 0) {
        float s = sqrtf(red[0] / (float)HH);
        g_thr[row] = T_CAND * s;
        g_keysafe[row] = fkey(xla_tanh(xla_tanh(T_SAFE * s)));
        g_cnt[row] = 0;
        g_flag[row] = 0;
    }
}

// ---------------- transposes ----------------------------------------------
__global__ void transpose_wout(const float* __restrict__ W) {
    __shared__ float tile[32][33];
    int x = blockIdx.x * 32 + threadIdx.x;
    int y = blockIdx.y * 32 + threadIdx.y;
#pragma unroll
    for (int i = 0; i < 32; i += 8)
        tile[threadIdx.y + i][threadIdx.x] = W[(size_t)(y + i) * VV + x];
    __syncthreads();
    int xo = blockIdx.y * 32 + threadIdx.x;
    int yo = blockIdx.x * 32 + threadIdx.y;
#pragma unroll
    for (int i = 0; i < 32; i += 8)
        g_wt[(size_t)(yo + i) * HH + xo] = tile[threadIdx.x][threadIdx.y + i];
}

__global__ void transpose_wbin(const float* __restrict__ W) {
    __shared__ float tile[32][33];
    int x = blockIdx.x * 32 + threadIdx.x;
    int y = blockIdx.y * 32 + threadIdx.y;
#pragma unroll
    for (int i = 0; i < 32; i += 8)
        tile[threadIdx.y + i][threadIdx.x] = W[(size_t)(y + i) * VV + x];
    __syncthreads();
    int xo = blockIdx.y * 32 + threadIdx.x;
    int yo = blockIdx.x * 32 + threadIdx.y;
#pragma unroll
    for (int i = 0; i < 32; i += 8) {
        float v = tile[threadIdx.x][threadIdx.y + i];
        g_wtb[(size_t)(yo + i) * HH + xo] = v;
        b_bf[(size_t)(yo + i) * HH + xo]  = __float2bfloat16(v);
    }
}

// ---------------- bf16 mma GEMM: 128x64 tile, 3 CTAs/SM -------------------
#define TM 128
#define TN 64
#define KSTEP 32
#define SSTR  40
#define MATE_A (TM * SSTR)             // 5120 elems
#define MATE_B (TN * SSTR)             // 2560 elems
#define STAGE_ELEMS (MATE_A + MATE_B)  // 7680 elems
#define NST   (HH / KSTEP)             // 16
#define DYN_SMEM (3 * STAGE_ELEMS * 2) // 46080 bytes

__global__ __launch_bounds__(256, 3) void mma_kernel() {
    extern __shared__ __align__(16) u16 smp[];

    const int tid  = threadIdx.x;
    const int warp = tid >> 5, lane = tid & 31;
    const int wm = warp & 3, wn = warp >> 2;      // 4 x 2 warp grid (32x32 each)
    const int gid = lane >> 2, qid = lane & 3;
    const int m0 = blockIdx.y * TM, n0 = blockIdx.x * TN;

    float c[2][4][4];
#pragma unroll
    for (int mi = 0; mi < 2; mi++)
#pragma unroll
        for (int ni = 0; ni < 4; ni++)
#pragma unroll
            for (int v = 0; v < 4; v++) c[mi][ni][v] = 0.f;

    const u16* Ag = (const u16*)a_bf + (size_t)m0 * HH;
    const u16* Bg = (const u16*)b_bf + (size_t)n0 * HH;
    // A: 128 rows x 32 cols -> 2 units/thread ; B: 64 rows x 32 cols -> 1 unit/thread
    const int arow = tid >> 1, acol = (tid & 1) * 16;
    const int brow = tid >> 2, bu = (tid & 3) * 8;

    const int lrow8 = ((lane >> 3) & 1) * 8 + (lane & 7);
    const int lcol8 = (lane >> 4) * 8;
    const unsigned smBase = (unsigned)__cvta_generic_to_shared(&smp[0]);
    const unsigned laneA = ((unsigned)((wm * 32 + lrow8) * SSTR + lcol8)) * 2u;
    const unsigned laneB = ((unsigned)((wn * 32 + lrow8) * SSTR + lcol8)) * 2u + (unsigned)(MATE_A * 2);

    auto load_stage = [&](int s) {
        u16* sb = smp + (s % 3) * STAGE_ELEMS;
        const int k0 = s * KSTEP;
        cp_async16(sb + arow * SSTR + acol,     Ag + (size_t)arow * HH + k0 + acol);
        cp_async16(sb + arow * SSTR + acol + 8, Ag + (size_t)arow * HH + k0 + acol + 8);
        cp_async16(sb + MATE_A + brow * SSTR + bu, Bg + (size_t)brow * HH + k0 + bu);
        asm volatile("cp.async.commit_group;");
    };

    load_stage(0);
    load_stage(1);

    for (int i = 0; i < NST; i++) {
        if (i + 2 < NST) asm volatile("cp.async.wait_group 1;");
        else             asm volatile("cp.async.wait_group 0;");
        __syncthreads();
        if (i + 2 < NST) load_stage(i + 2);

        const unsigned stOff = (unsigned)((i % 3) * STAGE_ELEMS * 2);
        const unsigned aB = smBase + stOff + laneA;
        const unsigned bB = smBase + stOff + laneB;

#pragma unroll
        for (int kk = 0; kk < KSTEP / 16; kk++) {
            unsigned a[2][4], b[4][2];
#pragma unroll
            for (int mi = 0; mi < 2; mi++)
                ldsm_x4(a[mi][0], a[mi][1], a[mi][2], a[mi][3],
                        aB + (unsigned)(mi * 16 * SSTR + kk * 16) * 2u);
#pragma unroll
            for (int p = 0; p < 2; p++)
                ldsm_x4(b[2 * p][0], b[2 * p + 1][0], b[2 * p][1], b[2 * p + 1][1],
                        bB + (unsigned)(p * 16 * SSTR + kk * 16) * 2u);
#pragma unroll
            for (int mi = 0; mi < 2; mi++)
#pragma unroll
                for (int ni = 0; ni < 4; ni++)
                    asm volatile(
                        "mma.sync.aligned.m16n8k16.row.col.f32.bf16.bf16.f32 "
                        "{%0,%1,%2,%3}, {%4,%5,%6,%7}, {%8,%9}, {%0,%1,%2,%3};"
                        : "+f"(c[mi][ni][0]), "+f"(c[mi][ni][1]),
                          "+f"(c[mi][ni][2]), "+f"(c[mi][ni][3])
                        : "r"(a[mi][0]), "r"(a[mi][1]), "r"(a[mi][2]), "r"(a[mi][3]),
                          "r"(b[ni][0]), "r"(b[ni][1]));
        }
    }

#pragma unroll
    for (int mi = 0; mi < 2; mi++) {
        const int r0 = m0 + wm * 32 + mi * 16 + gid;
        const int r1 = r0 + 8;
        const float t0 = g_thr[r0], t1 = g_thr[r1];
#pragma unroll
        for (int ni = 0; ni < 4; ni++) {
            const int cb = n0 + wn * 32 + ni * 8 + qid * 2;
#pragma unroll
            for (int v = 0; v < 4; v++) {
                const int row = (v < 2) ? r0 : r1;
                const float t = (v < 2) ? t0 : t1;
                const int col = cb + (v & 1);
                if (c[mi][ni][v] >= t) {
                    int pos = atomicAdd(&g_cnt[row], 1);
                    if (pos < CAP) g_cidx[(size_t)row * CAP + pos] = col;
                }
            }
        }
    }
}

// ---------------- exact rescore: staged smem tiles -------------------------
#define RT 128
#define KC 64
#define WPAD 68
__global__ __launch_bounds__(256) void rescore_kernel(const float* __restrict__ hs) {
    const int row = blockIdx.x, tid = threadIdx.x;
    __shared__ float hsm[HH];
    __shared__ __align__(16) float ws[RT][WPAD];
    __shared__ int cidxs[RT];

    for (int i = tid; i < HH / 4; i += 256)
        ((float4*)hsm)[i] = ((const float4*)(hs + (size_t)row * HH))[i];

    int cnt = g_cnt[row];
    if (cnt > CAP) cnt = CAP;

    const int grp = tid >> 4, gj = tid & 15;

    for (int base = 0; base < cnt; base += RT) {
        const int tcnt = min(RT, cnt - base);
        __syncthreads();
        if (tid < tcnt) cidxs[tid] = g_cidx[(size_t)row * CAP + base + tid];
        __syncthreads();

        float acc = 0.f;
        for (int kc = 0; kc < HH; kc += KC) {
#pragma unroll
            for (int p = 0; p < RT / 16; p++) {
                const int r = p * 16 + grp;
                if (r < tcnt)
                    *(float4*)&ws[r][gj * 4] =
                        *(const float4*)(g_wtb + (size_t)cidxs[r] * HH + kc + gj * 4);
            }
            __syncthreads();
            if (tid < tcnt) {
                const float* w = ws[tid];
#pragma unroll
                for (int k = 0; k < KC; k++)
                    acc = __fmaf_rn(hsm[kc + k], w[k], acc);
            }
            __syncthreads();
        }
        if (tid < tcnt) {
            const int idx = cidxs[tid];
            const unsigned key = fkey(xla_tanh(xla_tanh(acc)));
            g_cand[(size_t)row * CAP + base + tid] =
                ((u64)key << 32) | (u64)(0xFFFFFFFFu - (unsigned)idx);
        }
    }
}

// ---------------- sort + completeness verification ------------------------
__global__ __launch_bounds__(256) void topk_kernel() {
    const int row = blockIdx.x, tid = threadIdx.x;
    const int cnt = g_cnt[row];

    if (cnt < KK || cnt > CAP) {
        if (tid == 0) g_flag[row] = 1;
        return;
    }

    __shared__ u64 skey[CAP];
    int n = 512;
    while (n < cnt) n <<= 1;
    const u64* src = g_cand + (size_t)row * CAP;
    for (int i = tid; i < n; i += 256) skey[i] = (i < cnt) ? src[i] : 0ull;
    __syncthreads();

    for (int ks = 2; ks <= n; ks <<= 1) {
        for (int j = ks >> 1; j > 0; j >>= 1) {
            for (int i = tid; i < n; i += 256) {
                int ixj = i ^ j;
                if (ixj > i) {
                    u64 a = skey[i], b = skey[ixj];
                    bool up = ((i & ks) == 0);
                    if (up ? (a < b) : (a > b)) { skey[i] = b; skey[ixj] = a; }
                }
            }
            __syncthreads();
        }
    }

    if ((unsigned)(skey[KK - 1] >> 32) <= g_keysafe[row]) {
        if (tid == 0) g_flag[row] = 1;
        return;
    }
    for (int i = tid; i < KK; i += 256) {
        unsigned low = (unsigned)(skey[i] & 0xFFFFFFFFu);
        g_topk[(size_t)row * KK + i] = (int)(0xFFFFFFFFu - low);
    }
}

// ---------------- fallback part 1: exact keys, coalesced ------------------
#define FBT 32
#define FBC (VV / FBT)
__global__ __launch_bounds__(256) void fb_scores(const float* __restrict__ hs) {
    const int row = blockIdx.y;
    if (!g_flag[row]) return;
    const int tid = threadIdx.x;
    const int col0 = blockIdx.x * FBC;

    __shared__ float hsm[HH];
    __shared__ __align__(16) float ws[RT][WPAD];
    for (int i = tid; i < HH / 4; i += 256)
        ((float4*)hsm)[i] = ((const float4*)(hs + (size_t)row * HH))[i];

    const int grp = tid >> 4, gj = tid & 15;
    for (int base = 0; base < FBC; base += RT) {
        const int tcnt = min(RT, FBC - base);
        __syncthreads();
        float acc = 0.f;
        for (int kc = 0; kc < HH; kc += KC) {
#pragma unroll
            for (int p = 0; p < RT / 16; p++) {
                const int r = p * 16 + grp;
                if (r < tcnt)
                    *(float4*)&ws[r][gj * 4] =
                        *(const float4*)(g_wtb + (size_t)(col0 + base + r) * HH + kc + gj * 4);
            }
            __syncthreads();
            if (tid < tcnt) {
                const float* w = ws[tid];
#pragma unroll
                for (int k = 0; k < KC; k++)
                    acc = __fmaf_rn(hsm[kc + k], w[k], acc);
            }
            __syncthreads();
        }
        if (tid < tcnt)
            g_keys[(size_t)row * VV + col0 + base + tid] =
                fkey(xla_tanh(xla_tanh(acc)));
    }
}

// ---------------- fallback part 2: radix select ---------------------------
__global__ __launch_bounds__(256) void fb_topk() {
    const int row = blockIdx.x, tid = threadIdx.x;
    if (!g_flag[row]) return;
    const unsigned* s = g_keys + (size_t)row * VV;

    __shared__ unsigned hist[256];
    __shared__ unsigned sh_prefix;
    __shared__ int sh_k, n_gt, n_eq;
    __shared__ int eq_idx[128];
    __shared__ u64 skey[512];
    if (tid == 0) { sh_prefix = 0u; sh_k = KK; }
    __syncthreads();
    for (int pass = 3; pass >= 0; --pass) {
        hist[tid] = 0;
        __syncthreads();
        const unsigned prefix = sh_prefix;
        const unsigned mask_hi = (pass == 3) ? 0u : (0xFFFFFFFFu << ((pass + 1) * 8));
        const int shift = pass * 8;
        for (int i = tid; i < VV; i += 256) {
            unsigned u = s[i];
            if ((u & mask_hi) == prefix)
                atomicAdd(&hist[(u >> shift) & 0xFFu], 1u);
        }
        __syncthreads();
        if (tid == 0) {
            int k = sh_k;
            unsigned cum = 0;
            for (int b = 255; b >= 0; --b) {
                cum += hist[b];
                if ((int)cum >= k) {
                    sh_k = k - (int)(cum - hist[b]);
                    sh_prefix = prefix | ((unsigned)b << shift);
                    break;
                }
            }
        }
        __syncthreads();
    }
    const unsigned P = sh_prefix;
    const int kneed = sh_k;
    if (tid == 0) { n_gt = 0; n_eq = 0; }
    __syncthreads();
    for (int i = tid; i < 512; i += 256) skey[i] = 0ull;
    __syncthreads();
    for (int i = tid; i < VV; i += 256) {
        unsigned u = s[i];
        if (u > P) {
            int p = atomicAdd(&n_gt, 1);
            skey[p] = ((u64)u << 32) | (u64)(0xFFFFFFFFu - (unsigned)i);
        } else if (u == P) {
            int p = atomicAdd(&n_eq, 1);
            if (p < 128) eq_idx[p] = i;
        }
    }
    __syncthreads();
    if (tid == 0) {
        int ne = n_eq; if (ne > 128) ne = 128;
        for (int a = 1; a < ne; a++) {
            int v = eq_idx[a]; int b = a - 1;
            while (b >= 0 && eq_idx[b] > v) { eq_idx[b + 1] = eq_idx[b]; --b; }
            eq_idx[b + 1] = v;
        }
        int take = kneed; if (take > ne) take = ne;
        for (int a = 0; a < take; a++)
            skey[n_gt + a] = ((u64)P << 32) | (u64)(0xFFFFFFFFu - (unsigned)eq_idx[a]);
    }
    __syncthreads();
    for (int ks = 2; ks <= 512; ks <<= 1) {
        for (int j = ks >> 1; j > 0; j >>= 1) {
            for (int i = tid; i < 512; i += 256) {
                int ixj = i ^ j;
                if (ixj > i) {
                    u64 a = skey[i], b = skey[ixj];
                    bool up = ((i & ks) == 0);
                    if (up ? (a < b) : (a > b)) { skey[i] = b; skey[ixj] = a; }
                }
            }
            __syncthreads();
        }
    }
    for (int i = tid; i < KK; i += 256) {
        unsigned low = (unsigned)(skey[i] & 0xFFFFFFFFu);
        g_topk[(size_t)row * KK + i] = (int)(0xFFFFFFFFu - low);
    }
}

// ---------------- fused zero + gathered dot + scatter ----------------------
__global__ __launch_bounds__(256) void scatter_kernel(
    const float* __restrict__ hs, float* __restrict__ out_logits,
    float* __restrict__ out_idx)
{
    const int row = blockIdx.x;
    const int tid = threadIdx.x;
    __shared__ float4 h4[HH / 4];
    for (int i = tid; i < HH / 4; i += 256)
        h4[i] = ((const float4*)(hs + (size_t)row * HH))[i];

    float4* orow4 = (float4*)(out_logits + (size_t)row * VV);
    const float4 z4 = make_float4(0.f, 0.f, 0.f, 0.f);
    for (int i = tid; i < VV / 4; i += 256) orow4[i] = z4;
    __syncthreads();

    const int warp = tid >> 5, lane = tid & 31;
    for (int c = warp; c < KK; c += 8) {
        int idx = g_topk[(size_t)row * KK + c];
        const float4* w4 = (const float4*)(g_wt + (size_t)idx * HH);
        float sum = 0.f;
#pragma unroll
        for (int t = lane; t < HH / 4; t += 32) {
            float4 a = h4[t], b = w4[t];
            sum = fmaf(a.x, b.x, sum);
            sum = fmaf(a.y, b.y, sum);
            sum = fmaf(a.z, b.z, sum);
            sum = fmaf(a.w, b.w, sum);
        }
#pragma unroll
        for (int o = 16; o > 0; o >>= 1) sum += __shfl_down_sync(0xFFFFFFFFu, sum, o);
        if (lane == 0) {
            out_logits[(size_t)row * VV + idx] = sum;
            out_idx[(size_t)row * KK + c] = (float)idx;
        }
    }
}

// ---------------- launch --------------------------------------------------
extern "C" void kernel_launch(void* const* d_in, const int* in_sizes, int n_in,
                              void* d_out, int out_size) {
    const float* hs    = (const float*)d_in[0];
    const float* w_out = (const float*)d_in[1];
    const float* w_bin = (const float*)d_in[2];
    float* out = (float*)d_out;

    cudaFuncSetAttribute(mma_kernel,
                         cudaFuncAttributeMaxDynamicSharedMemorySize, DYN_SMEM);

    const size_t logitsN = (size_t)MM * VV;

    prep_kernel<<<MM, 256, 0, 0>>>(hs);
    transpose_wout<<<dim3(VV / 32, HH / 32), dim3(32, 8), 0, 0>>>(w_out);
    transpose_wbin<<<dim3(VV / 32, HH / 32), dim3(32, 8), 0, 0>>>(w_bin);
    mma_kernel<<<dim3(VV / TN, MM / TM), 256, DYN_SMEM, 0>>>();
    rescore_kernel<<<MM, 256, 0, 0>>>(hs);
    topk_kernel<<<MM, 256, 0, 0>>>();
    fb_scores<<<dim3(FBT, MM), 256, 0, 0>>>(hs);
    fb_topk<<<MM, 256, 0, 0>>>();
    scatter_kernel<<<MM, 256, 0, 0>>>(hs, out, out + logitsN);
}